// round 3
// baseline (speedup 1.0000x reference)
#include <cuda_runtime.h>

// CausalWindowedAttention: B=2,H=16,S=2048,D=64, window=256, temp=8
// Output = concat(out[B,H,S,D], attn[B,H,S,S]) as float32.

#define SQ    2048
#define DH    64
#define MT    64              // queries per CTA tile
#define WIN   256
#define KR    320             // valid key rows for the tile window union
#define KRA   352             // allocated key rows (zero-padded tail)
#define KPAD  68              // padded K/V row (floats)
#define SPAD  353             // score row stride (floats)
#define NTH   512

// smem layout (floats)
#define SM_Q   0
#define SM_K   (MT * DH)                  // 4096
#define SM_S   (SM_K + KRA * KPAD)        // 4096 + 23936 = 28032
#define SM_TOT (SM_S + MT * SPAD)         // 28032 + 22592 = 50624 floats = 202496 B

__device__ __forceinline__ void ffma2(unsigned long long& d,
                                      unsigned long long a,
                                      unsigned long long b) {
    asm("fma.rn.f32x2 %0, %1, %2, %0;" : "+l"(d) : "l"(a), "l"(b));
}
__device__ __forceinline__ unsigned long long pk2(float x) {
    unsigned long long r;
    asm("mov.b64 %0, {%1, %1};" : "=l"(r) : "f"(x));
    return r;
}
__device__ __forceinline__ float unpk_sum(unsigned long long a) {
    float lo, hi;
    asm("mov.b64 {%0, %1}, %2;" : "=f"(lo), "=f"(hi) : "l"(a));
    return lo + hi;
}

__global__ void __launch_bounds__(NTH, 1)
cwa_kernel(const float* __restrict__ q,
           const float* __restrict__ k,
           const float* __restrict__ v,
           float* __restrict__ out,    // [BH, SQ, DH]
           float* __restrict__ attn)   // [BH, SQ, SQ]
{
    extern __shared__ float sm[];
    float* sQ = sm + SM_Q;
    float* sK = sm + SM_K;   // reused for V later
    float* sS = sm + SM_S;

    const int tile = blockIdx.x;
    const int bh   = blockIdx.y;
    const int i0   = tile * MT;
    const int tid  = threadIdx.x;
    const int lane = tid & 31;
    const int w    = tid >> 5;

    const size_t base = (size_t)bh * SQ * DH;
    const size_t attn_base = (size_t)bh * SQ * SQ;
    const int jn0 = i0 - (WIN - 1);   // key j for smem row n: j = jn0 + n

    // ---- load Q tile (64 x 64) ----
    {
        const float4* qg = (const float4*)(q + base + (size_t)i0 * DH);
        float4* qs = (float4*)sQ;
        for (int idx = tid; idx < MT * (DH / 4); idx += NTH)
            qs[idx] = qg[idx];
    }
    // ---- load K window (352 rows, zero-fill OOB) ----
    for (int idx = tid; idx < KRA * (DH / 4); idx += NTH) {
        int n = idx >> 4;
        int c = idx & 15;
        int j = jn0 + n;
        float4 val = make_float4(0.f, 0.f, 0.f, 0.f);
        if (j >= 0 && j < SQ)
            val = *(const float4*)(k + base + (size_t)j * DH + c * 4);
        *(float4*)&sK[n * KPAD + c * 4] = val;
    }

    // ---- zero-store pass: attn outside the band depends on nothing; issue
    //      it NOW so the DRAM write stream drains under QK/softmax compute.
    //      Warp w owns rows w*4 .. w*4+3. Band float4 range [jlo4, jhi4]
    //      (inclusive) is left for the band pass after softmax.
    {
        const float4 z4 = make_float4(0.f, 0.f, 0.f, 0.f);
        #pragma unroll
        for (int r = 0; r < 4; r++) {
            const int m = w * 4 + r;
            const int i = i0 + m;
            const int jlo = max(0, i - (WIN - 1));
            const int jlo4 = jlo >> 2;
            const int jhi4 = i >> 2;
            float4* dst = (float4*)(attn + attn_base + (size_t)i * SQ);
            for (int idx = lane; idx < jlo4; idx += 32)
                dst[idx] = z4;
            for (int idx = jhi4 + 1 + lane; idx < SQ / 4; idx += 32)
                dst[idx] = z4;
        }
    }
    __syncthreads();

    // ---- scores: warp w -> rows m0..m0+3, keys n = m0 + lane + 32*ni, ni<9 ----
    {
        const int m0 = w * 4;
        int nb[9];
        #pragma unroll
        for (int ni = 0; ni < 9; ni++)
            nb[ni] = (m0 + lane + 32 * ni) * KPAD;

        unsigned long long acc[4][9];
        #pragma unroll
        for (int mi = 0; mi < 4; mi++)
            #pragma unroll
            for (int ni = 0; ni < 9; ni++)
                acc[mi][ni] = 0ULL;

        #pragma unroll 1
        for (int dc = 0; dc < DH / 4; dc++) {
            ulonglong2 q2[4];
            #pragma unroll
            for (int mi = 0; mi < 4; mi++)
                q2[mi] = *(const ulonglong2*)&sQ[(m0 + mi) * DH + dc * 4];
            #pragma unroll
            for (int ni = 0; ni < 9; ni++) {
                ulonglong2 k2 = *(const ulonglong2*)&sK[nb[ni] + dc * 4];
                #pragma unroll
                for (int mi = 0; mi < 4; mi++) {
                    ffma2(acc[mi][ni], q2[mi].x, k2.x);
                    ffma2(acc[mi][ni], q2[mi].y, k2.y);
                }
            }
        }
        #pragma unroll
        for (int mi = 0; mi < 4; mi++)
            #pragma unroll
            for (int ni = 0; ni < 9; ni++)
                sS[(m0 + mi) * SPAD + m0 + lane + 32 * ni] =
                    unpk_sum(acc[mi][ni]) * 0.125f;   // 1/temperature
    }
    __syncthreads();

    // ---- softmax per row (warp w owns rows w*4..w*4+3), zero outside window ----
    {
        const int m0 = w * 4;
        #pragma unroll 1
        for (int r = 0; r < 4; r++) {
            const int m = m0 + r;
            const int nlo = max(m, (WIN - 1) - i0);  // j>=0 clamp
            const int nhi = m + (WIN - 1);

            float mx = -1e30f;
            for (int n = nlo + lane; n <= nhi; n += 32)
                mx = fmaxf(mx, sS[m * SPAD + n]);
            #pragma unroll
            for (int o = 16; o; o >>= 1)
                mx = fmaxf(mx, __shfl_xor_sync(0xffffffffu, mx, o));

            float sum = 0.f;
            for (int n = nlo + lane; n <= nhi; n += 32) {
                float e = __expf(sS[m * SPAD + n] - mx);
                sS[m * SPAD + n] = e;
                sum += e;
            }
            #pragma unroll
            for (int o = 16; o; o >>= 1)
                sum += __shfl_xor_sync(0xffffffffu, sum, o);

            const float inv = 1.f / sum;
            for (int n = lane; n < KRA; n += 32) {
                float val = (n >= nlo && n <= nhi) ? sS[m * SPAD + n] * inv : 0.f;
                sS[m * SPAD + n] = val;
            }
        }
    }
    __syncthreads();

    if (tid < 256) {
        // ===== warps 0-7: load V, then PV, write out =====
        for (int idx = tid; idx < KR * (DH / 4); idx += 256) {
            int n = idx >> 4;
            int c = idx & 15;
            int j = jn0 + n;
            float4 val = make_float4(0.f, 0.f, 0.f, 0.f);
            if (j >= 0 && j < SQ)
                val = *(const float4*)(v + base + (size_t)j * DH + c * 4);
            *(float4*)&sK[n * KPAD + c * 4] = val;
        }
        asm volatile("bar.sync 1, 256;" ::: "memory");

        const int dq = tid & 15;          // d-group: cols dq*4..dq*4+3
        const int mg = tid >> 4;          // row group: rows mg*4..mg*4+3
        const float* pbase = sS + (mg * 4) * SPAD;

        unsigned long long axy[4], azw[4];
        #pragma unroll
        for (int r = 0; r < 4; r++) { axy[r] = 0ULL; azw[r] = 0ULL; }

        #pragma unroll 4
        for (int n = 0; n < KR; n++) {
            ulonglong2 v2 = *(const ulonglong2*)&sK[n * KPAD + dq * 4];
            #pragma unroll
            for (int r = 0; r < 4; r++) {
                unsigned long long p2 = pk2(pbase[r * SPAD + n]);
                ffma2(axy[r], p2, v2.x);
                ffma2(azw[r], p2, v2.y);
            }
        }
        #pragma unroll
        for (int r = 0; r < 4; r++) {
            ulonglong2 o;
            o.x = axy[r];
            o.y = azw[r];
            *(ulonglong2*)(out + base + (size_t)(i0 + mg * 4 + r) * DH + dq * 4) = o;
        }
    } else {
        // ===== warps 8-15: write the band segments only (~66 float4/row) =====
        const int tw = tid - 256;
        const int lw = tw & 31;
        const int ww = tw >> 5;           // 0..7, rows ww*8..ww*8+7

        #pragma unroll 1
        for (int rr = 0; rr < 8; rr++) {
            const int m = ww * 8 + rr;
            const int i = i0 + m;
            const int jlo = max(0, i - (WIN - 1));
            const int jlo4 = jlo >> 2;
            const int jhi4 = i >> 2;
            float4* dst = (float4*)(attn + attn_base + (size_t)i * SQ);
            const float* srow = sS + m * SPAD - jn0;   // srow[j] = prob(i, j)

            for (int idx4 = jlo4 + lw; idx4 <= jhi4; idx4 += 32) {
                const int j4 = idx4 * 4;
                float4 val;
                float* vp = &val.x;
                #pragma unroll
                for (int c = 0; c < 4; c++) {
                    const int j = j4 + c;
                    vp[c] = (j >= jlo && j <= i) ? srow[j] : 0.f;
                }
                dst[idx4] = val;
            }
        }
    }
}

extern "C" void kernel_launch(void* const* d_in, const int* in_sizes, int n_in,
                              void* d_out, int out_size)
{
    const float* q = (const float*)d_in[0];
    const float* k = (const float*)d_in[1];
    const float* v = (const float*)d_in[2];

    const int BH = in_sizes[0] / (SQ * DH);   // 32

    float* out  = (float*)d_out;
    float* attn = out + (size_t)BH * SQ * DH;

    cudaFuncSetAttribute(cwa_kernel,
                         cudaFuncAttributeMaxDynamicSharedMemorySize,
                         SM_TOT * (int)sizeof(float));

    dim3 grid(SQ / MT, BH);
    cwa_kernel<<<grid, NTH, SM_TOT * sizeof(float)>>>(q, k, v, out, attn);
    (void)n_in; (void)out_size;
}

// round 4
// speedup vs baseline: 1.1549x; 1.1549x over previous
#include <cuda_runtime.h>
#include <cstdint>

// CausalWindowedAttention: B=2,H=16,S=2048,D=64, window=256, temp=8
// Output = concat(out[B,H,S,D], attn[B,H,S,S]) as float32.
// attn rows written via cp.async.bulk (TMA bulk stores): zero prefix/suffix
// from a zero SMEM buffer (issued early), band segment from the score buffer.

#define SQ    2048
#define DH    64
#define MT    64              // queries per CTA tile
#define WIN   256
#define KR    320             // valid key rows for the tile window union
#define KRA   352             // allocated key rows (zero-padded tail)
#define KPAD  68              // padded K/V row (floats)
#define SROW  328             // score row stride: 4 slack + up to 324 offsets
#define NTH   512

// smem layout (floats)
#define SM_Q   0
#define SM_K   (MT * DH)                  // 4096
#define SM_S   (SM_K + KRA * KPAD)        // 28032
#define SM_Z   (SM_S + MT * SROW)         // 49024
#define SM_TOT (SM_Z + 2048)              // 51072 floats = 204288 B

__device__ __forceinline__ void ffma2(unsigned long long& d,
                                      unsigned long long a,
                                      unsigned long long b) {
    asm("fma.rn.f32x2 %0, %1, %2, %0;" : "+l"(d) : "l"(a), "l"(b));
}
__device__ __forceinline__ unsigned long long pk2(float x) {
    unsigned long long r;
    asm("mov.b64 %0, {%1, %1};" : "=l"(r) : "f"(x));
    return r;
}
__device__ __forceinline__ float unpk_sum(unsigned long long a) {
    float lo, hi;
    asm("mov.b64 {%0, %1}, %2;" : "=f"(lo), "=f"(hi) : "l"(a));
    return lo + hi;
}
__device__ __forceinline__ uint32_t s2u(const void* p) {
    return (uint32_t)__cvta_generic_to_shared(p);
}
__device__ __forceinline__ void bulk_store(void* gdst, uint32_t ssrc, uint32_t bytes) {
    asm volatile("cp.async.bulk.global.shared::cta.bulk_group [%0], [%1], %2;"
                 :: "l"(gdst), "r"(ssrc), "r"(bytes) : "memory");
}
__device__ __forceinline__ void fence_async() {
    asm volatile("fence.proxy.async.shared::cta;" ::: "memory");
}

__global__ void __launch_bounds__(NTH, 1)
cwa_kernel(const float* __restrict__ q,
           const float* __restrict__ k,
           const float* __restrict__ v,
           float* __restrict__ out,    // [BH, SQ, DH]
           float* __restrict__ attn)   // [BH, SQ, SQ]
{
    extern __shared__ float sm[];
    float* sQ = sm + SM_Q;
    float* sK = sm + SM_K;   // reused for V later
    float* sS = sm + SM_S;   // 64 rows x SROW; row m offsets indexed [-4, 324)
    float* sZ = sm + SM_Z;   // 2048 zero floats

    const int tile = blockIdx.x;
    const int bh   = blockIdx.y;
    const int i0   = tile * MT;
    const int tid  = threadIdx.x;
    const int lane = tid & 31;
    const int w    = tid >> 5;

    const size_t base = (size_t)bh * SQ * DH;
    const size_t attn_base = (size_t)bh * SQ * SQ;
    const int jn0 = i0 - (WIN - 1);   // key j for smem key-row n: j = jn0 + n

    // ---- load Q tile (64 x 64) ----
    {
        const float4* qg = (const float4*)(q + base + (size_t)i0 * DH);
        float4* qs = (float4*)sQ;
        for (int idx = tid; idx < MT * (DH / 4); idx += NTH)
            qs[idx] = qg[idx];
    }
    // ---- load K window (352 rows, zero-fill OOB) ----
    for (int idx = tid; idx < KRA * (DH / 4); idx += NTH) {
        int n = idx >> 4;
        int c = idx & 15;
        int j = jn0 + n;
        float4 val = make_float4(0.f, 0.f, 0.f, 0.f);
        if (j >= 0 && j < SQ)
            val = *(const float4*)(k + base + (size_t)j * DH + c * 4);
        *(float4*)&sK[n * KPAD + c * 4] = val;
    }
    // ---- zero buffer ----
    {
        float4* zs = (float4*)sZ;
        const float4 z4 = make_float4(0.f, 0.f, 0.f, 0.f);
        for (int idx = tid; idx < 2048 / 4; idx += NTH)
            zs[idx] = z4;
    }
    __syncthreads();

    // ---- issue zero prefix/suffix bulk stores for all 64 rows NOW:
    //      they depend on nothing, so the DRAM write stream drains under
    //      the QK/softmax compute. Thread t < 64 owns row t.
    if (tid < MT) {
        const int m = tid;
        const int i = i0 + m;
        const int jlo = max(0, i - (WIN - 1));
        const int jstart4 = jlo & ~3;
        const int jend4 = (i + 4) & ~3;           // exclusive, multiple of 4
        float* dst = attn + attn_base + (size_t)i * SQ;
        const uint32_t zaddr = s2u(sZ);
        fence_async();
        const uint32_t pb = (uint32_t)jstart4 * 4u;
        if (pb) bulk_store(dst, zaddr, pb);
        const uint32_t sb = (uint32_t)(SQ - jend4) * 4u;
        if (sb) bulk_store(dst + jend4, zaddr, sb);
    }

    // ---- scores: warp w -> rows m0..m0+3, keys n = m0 + lane + 32*ni, ni<9.
    //      Row m storage: sS[m*SROW + 4 + off], off = j - jstart4(m) = n - s[mi].
    const int m0 = w * 4;
    int srow_s[4];       // s[mi] = jstart4(m) - jn0
    {
        #pragma unroll
        for (int mi = 0; mi < 4; mi++) {
            const int i = i0 + m0 + mi;
            const int jlo = max(0, i - (WIN - 1));
            srow_s[mi] = (jlo & ~3) - jn0;
        }

        int nb[9];
        #pragma unroll
        for (int ni = 0; ni < 9; ni++)
            nb[ni] = (m0 + lane + 32 * ni) * KPAD;

        unsigned long long acc[4][9];
        #pragma unroll
        for (int mi = 0; mi < 4; mi++)
            #pragma unroll
            for (int ni = 0; ni < 9; ni++)
                acc[mi][ni] = 0ULL;

        #pragma unroll 1
        for (int dc = 0; dc < DH / 4; dc++) {
            ulonglong2 q2[4];
            #pragma unroll
            for (int mi = 0; mi < 4; mi++)
                q2[mi] = *(const ulonglong2*)&sQ[(m0 + mi) * DH + dc * 4];
            #pragma unroll
            for (int ni = 0; ni < 9; ni++) {
                ulonglong2 k2 = *(const ulonglong2*)&sK[nb[ni] + dc * 4];
                #pragma unroll
                for (int mi = 0; mi < 4; mi++) {
                    ffma2(acc[mi][ni], q2[mi].x, k2.x);
                    ffma2(acc[mi][ni], q2[mi].y, k2.y);
                }
            }
        }
        #pragma unroll
        for (int mi = 0; mi < 4; mi++) {
            float* rp = sS + (m0 + mi) * SROW + 4;
            #pragma unroll
            for (int ni = 0; ni < 9; ni++) {
                const int n = m0 + lane + 32 * ni;
                const int off = n - srow_s[mi];
                if ((unsigned)(off + 4) < (unsigned)SROW)
                    rp[off] = unpk_sum(acc[mi][ni]) * 0.125f;  // 1/temperature
            }
        }
    }
    // (scores for warp's rows are warp-local: no __syncthreads needed)

    // ---- softmax per row; zero-fill the full [-4,324) range outside band ----
    {
        #pragma unroll 1
        for (int r = 0; r < 4; r++) {
            const int m = m0 + r;
            const int i = i0 + m;
            const int jlo = max(0, i - (WIN - 1));
            const int off_lo = jlo & 3;
            const int off_hi = i - (jlo & ~3);
            float* rp = sS + m * SROW + 4;

            float mx = -1e30f;
            for (int off = off_lo + lane; off <= off_hi; off += 32)
                mx = fmaxf(mx, rp[off]);
            #pragma unroll
            for (int o = 16; o; o >>= 1)
                mx = fmaxf(mx, __shfl_xor_sync(0xffffffffu, mx, o));

            float sum = 0.f;
            for (int off = off_lo + lane; off <= off_hi; off += 32) {
                float e = __expf(rp[off] - mx);
                rp[off] = e;
                sum += e;
            }
            #pragma unroll
            for (int o = 16; o; o >>= 1)
                sum += __shfl_xor_sync(0xffffffffu, sum, o);

            const float inv = 1.f / sum;
            for (int off = -4 + lane; off < SROW - 4; off += 32) {
                float val = (off >= off_lo && off <= off_hi) ? rp[off] * inv : 0.f;
                rp[off] = val;
            }
        }
    }
    __syncthreads();

    // ---- issue band bulk stores (lane < 4 of each warp owns row m0+lane) ----
    if (lane < 4) {
        const int m = m0 + lane;
        const int i = i0 + m;
        const int jlo = max(0, i - (WIN - 1));
        const int jstart4 = jlo & ~3;
        const int jend4 = (i + 4) & ~3;
        fence_async();
        bulk_store(attn + attn_base + (size_t)i * SQ + jstart4,
                   s2u(sS + m * SROW + 4),
                   (uint32_t)(jend4 - jstart4) * 4u);
    }

    // ---- load V into the K buffer ----
    for (int idx = tid; idx < KR * (DH / 4); idx += NTH) {
        int n = idx >> 4;
        int c = idx & 15;
        int j = jn0 + n;
        float4 val = make_float4(0.f, 0.f, 0.f, 0.f);
        if (j >= 0 && j < SQ)
            val = *(const float4*)(v + base + (size_t)j * DH + c * 4);
        *(float4*)&sK[n * KPAD + c * 4] = val;
    }
    __syncthreads();

    // ---- PV: all 512 threads; thread owns rows {2mg, 2mg+1} x d-quad dq ----
    {
        const int dq = tid & 15;          // d cols dq*4..dq*4+3
        const int mg = tid >> 4;          // row pair index 0..31
        const int r0 = 2 * mg;
        const int r1 = r0 + 1;

        const int i0r = i0 + r0;
        const int jlo0 = max(0, i0r - (WIN - 1));
        const int jlo1 = max(0, i0r + 1 - (WIN - 1));
        const int s0 = (jlo0 & ~3) - jn0;
        const int s1 = (jlo1 & ~3) - jn0;

        // rpX[n] reads offset (n - sX) of row rX; defined (zero) on [-4,324)
        const float* rp0 = sS + r0 * SROW + 4 - s0;
        const float* rp1 = sS + r1 * SROW + 4 - s1;

        const int nlo_cta = max(0, -jn0);        // keys with j < 0 excluded
        const int n_start = max(r0, nlo_cta);
        const int n_end = r0 + 256;              // inclusive; <= 318

        unsigned long long a0x = 0ULL, a0z = 0ULL, a1x = 0ULL, a1z = 0ULL;

        #pragma unroll 4
        for (int n = n_start; n <= n_end; n++) {
            ulonglong2 v2 = *(const ulonglong2*)&sK[n * KPAD + dq * 4];
            unsigned long long p0 = pk2(rp0[n]);
            unsigned long long p1 = pk2(rp1[n]);
            ffma2(a0x, p0, v2.x);
            ffma2(a0z, p0, v2.y);
            ffma2(a1x, p1, v2.x);
            ffma2(a1z, p1, v2.y);
        }

        ulonglong2 o0; o0.x = a0x; o0.y = a0z;
        ulonglong2 o1; o1.x = a1x; o1.y = a1z;
        *(ulonglong2*)(out + base + (size_t)(i0 + r0) * DH + dq * 4) = o0;
        *(ulonglong2*)(out + base + (size_t)(i0 + r1) * DH + dq * 4) = o1;
    }

    // ---- ensure all bulk stores complete before kernel end ----
    asm volatile("cp.async.bulk.commit_group;" ::: "memory");
    asm volatile("cp.async.bulk.wait_group 0;" ::: "memory");
}

extern "C" void kernel_launch(void* const* d_in, const int* in_sizes, int n_in,
                              void* d_out, int out_size)
{
    const float* q = (const float*)d_in[0];
    const float* k = (const float*)d_in[1];
    const float* v = (const float*)d_in[2];

    const int BH = in_sizes[0] / (SQ * DH);   // 32

    float* out  = (float*)d_out;
    float* attn = out + (size_t)BH * SQ * DH;

    cudaFuncSetAttribute(cwa_kernel,
                         cudaFuncAttributeMaxDynamicSharedMemorySize,
                         SM_TOT * (int)sizeof(float));

    dim3 grid(SQ / MT, BH);
    cwa_kernel<<<grid, NTH, SM_TOT * sizeof(float)>>>(q, k, v, out, attn);
    (void)n_in; (void)out_size;
}